// round 1
// baseline (speedup 1.0000x reference)
#include <cuda_runtime.h>
#include <math.h>

#define B_ 4
#define S_ 2048
#define H_ 16
#define D_ 64
#define E_ 1024
#define E3_ 3072
#define BH_ (B_*H_)

// Scratch (device globals: allocation-free rule)
__device__ float g_q[B_*H_*S_*D_];     // 32 MB, [b,h,s,d]
__device__ float g_k[B_*H_*S_*D_];
__device__ float g_v[B_*H_*S_*D_];
__device__ float g_attn[B_*S_*E_];     // 32 MB, [b,s,h*d] (merged heads)

// ---------------------------------------------------------------------------
// SGEMM: C[M,N] = A[M,K] @ B[K,N] + bias.  128x128 tile, BK=8, 256 threads,
// 8x8 per-thread microtile split as (4+4)x(4+4) for conflict-free float4 LDS.
// EPI=1: scatter into g_q/g_k/g_v with [b,h,s,d] layout (QKV projection)
// EPI=0: plain row-major store (output projection)
// ---------------------------------------------------------------------------
template<int EPI>
__global__ __launch_bounds__(256)
void sgemm128(const float* __restrict__ A, const float* __restrict__ Bm,
              const float* __restrict__ bias, float* __restrict__ C,
              int M, int N, int K)
{
    __shared__ float As[8][128];
    __shared__ float Bs[8][128];

    const int t  = threadIdx.x;
    const int tx = t & 15;
    const int ty = t >> 4;
    const int bm = blockIdx.y * 128;
    const int bn = blockIdx.x * 128;

    // load maps
    const int arow  = t >> 1;          // 0..127
    const int acol4 = (t & 1) * 4;     // 0 or 4
    const int brow  = t >> 5;          // 0..7
    const int bcol4 = (t & 31) * 4;    // 0..124

    const float* Aptr = A + (long)(bm + arow) * K + acol4;
    const float* Bptr = Bm + (long)brow * N + bn + bcol4;

    float acc[8][8];
#pragma unroll
    for (int i = 0; i < 8; i++)
#pragma unroll
        for (int j = 0; j < 8; j++) acc[i][j] = 0.f;

    for (int k0 = 0; k0 < K; k0 += 8) {
        float4 av = *(const float4*)(Aptr + k0);
        float4 bv = *(const float4*)(Bptr + (long)k0 * N);
        As[acol4 + 0][arow] = av.x;
        As[acol4 + 1][arow] = av.y;
        As[acol4 + 2][arow] = av.z;
        As[acol4 + 3][arow] = av.w;
        *(float4*)&Bs[brow][bcol4] = bv;
        __syncthreads();

#pragma unroll
        for (int k = 0; k < 8; k++) {
            float af[8], bf[8];
            *(float4*)(af + 0) = *(const float4*)&As[k][ty * 4];
            *(float4*)(af + 4) = *(const float4*)&As[k][64 + ty * 4];
            *(float4*)(bf + 0) = *(const float4*)&Bs[k][tx * 4];
            *(float4*)(bf + 4) = *(const float4*)&Bs[k][64 + tx * 4];
#pragma unroll
            for (int i = 0; i < 8; i++)
#pragma unroll
                for (int j = 0; j < 8; j++)
                    acc[i][j] += af[i] * bf[j];
        }
        __syncthreads();
    }

    // epilogue
#pragma unroll
    for (int ig = 0; ig < 2; ig++) {
#pragma unroll
        for (int i2 = 0; i2 < 4; i2++) {
            const int i = ig * 4 + i2;
            const int r = bm + ig * 64 + ty * 4 + i2;
#pragma unroll
            for (int jg = 0; jg < 2; jg++) {
                const int c0 = bn + jg * 64 + tx * 4;
                float4 bias4 = *(const float4*)(bias + c0);
                float4 v;
                v.x = acc[i][jg * 4 + 0] + bias4.x;
                v.y = acc[i][jg * 4 + 1] + bias4.y;
                v.z = acc[i][jg * 4 + 2] + bias4.z;
                v.w = acc[i][jg * 4 + 3] + bias4.w;
                if (EPI == 1) {
                    // scatter into q/k/v [b,h,s,d]
                    const int b   = r >> 11;        // r / 2048
                    const int si  = r & 2047;
                    const int sec = c0 >> 10;       // 0=q 1=k 2=v
                    const int win = c0 & 1023;
                    const int h   = win >> 6;
                    const int d   = win & 63;
                    float* dst = (sec == 0) ? g_q : (sec == 1) ? g_k : g_v;
                    *(float4*)&dst[(((long)(b * H_ + h)) * S_ + si) * D_ + d] = v;
                } else {
                    *(float4*)&C[(long)r * N + c0] = v;
                }
            }
        }
    }
}

// ---------------------------------------------------------------------------
// Flash-style attention, fp32.  One block = one (b,h) x 64-query tile.
// 256 threads: thread (tx,ty) owns queries qi=ty*4+i, cols/keys tx*4+j.
// Streams 64-key tiles: S = Q K^T * 0.125 (K staged transposed, pad 68),
// online softmax, P staged in smem, O += P V (V natural layout).
// ---------------------------------------------------------------------------
#define KTPAD 68
#define ATTN_SMEM ((64*64 + 64*KTPAD + 64*64 + 64*KTPAD + 64) * 4)

__global__ __launch_bounds__(256)
void attn_kernel(const int* __restrict__ mask)
{
    extern __shared__ float sm[];
    float* Qs = sm;                     // [64][64]
    float* Kt = Qs + 64 * 64;           // [64][KTPAD]  (d-major, transposed)
    float* Vs = Kt + 64 * KTPAD;        // [64][64]
    float* Ps = Vs + 64 * 64;           // [64][KTPAD]
    float* Mf = Ps + 64 * KTPAD;        // [64]

    const int t    = threadIdx.x;
    const int tx   = t & 15;
    const int ty   = t >> 4;
    const int qblk = blockIdx.x;
    const int bh   = blockIdx.y;
    const int b    = bh >> 4;
    const int h    = bh & 15;

    const float* Qg = g_q + ((long)bh * S_ + qblk * 64) * D_;
    const float* Kg = g_k + (long)bh * S_ * D_;
    const float* Vg = g_v + (long)bh * S_ * D_;
    const int* mrow = mask + b * S_;

    // load Q tile (natural layout)
    for (int i = t; i < 64 * 16; i += 256) {
        const int r  = i >> 4;
        const int c4 = (i & 15) * 4;
        *(float4*)&Qs[r * 64 + c4] = *(const float4*)&Qg[r * 64 + c4];
    }

    float m_i[4], l_i[4], o_[4][4];
#pragma unroll
    for (int i = 0; i < 4; i++) {
        m_i[i] = -1e30f; l_i[i] = 0.f;
#pragma unroll
        for (int j = 0; j < 4; j++) o_[i][j] = 0.f;
    }

    for (int kt0 = 0; kt0 < S_; kt0 += 64) {
        __syncthreads();   // protect smem from previous iteration's readers
        // stage K transposed + V natural + mask
        for (int i = t; i < 64 * 16; i += 256) {
            const int r = i >> 4;
            const int a = i & 15;
            float4 kv = *(const float4*)&Kg[(long)(kt0 + r) * D_ + a * 4];
            Kt[(a * 4 + 0) * KTPAD + r] = kv.x;
            Kt[(a * 4 + 1) * KTPAD + r] = kv.y;
            Kt[(a * 4 + 2) * KTPAD + r] = kv.z;
            Kt[(a * 4 + 3) * KTPAD + r] = kv.w;
            *(float4*)&Vs[r * 64 + a * 4] =
                *(const float4*)&Vg[(long)(kt0 + r) * D_ + a * 4];
        }
        if (t < 64) Mf[t] = (mrow[kt0 + t] != 0) ? 1.0f : 0.0f;
        __syncthreads();

        // scores: s[i][j] = sum_d Q[qi][d] * K[kj][d]
        float s_[4][4];
#pragma unroll
        for (int i = 0; i < 4; i++)
#pragma unroll
            for (int j = 0; j < 4; j++) s_[i][j] = 0.f;

#pragma unroll 4
        for (int d4 = 0; d4 < 16; d4++) {
            float4 k0v = *(const float4*)&Kt[(d4 * 4 + 0) * KTPAD + tx * 4];
            float4 k1v = *(const float4*)&Kt[(d4 * 4 + 1) * KTPAD + tx * 4];
            float4 k2v = *(const float4*)&Kt[(d4 * 4 + 2) * KTPAD + tx * 4];
            float4 k3v = *(const float4*)&Kt[(d4 * 4 + 3) * KTPAD + tx * 4];
#pragma unroll
            for (int i = 0; i < 4; i++) {
                float4 q4 = *(const float4*)&Qs[(ty * 4 + i) * 64 + d4 * 4];
                s_[i][0] += q4.x * k0v.x; s_[i][0] += q4.y * k1v.x;
                s_[i][0] += q4.z * k2v.x; s_[i][0] += q4.w * k3v.x;
                s_[i][1] += q4.x * k0v.y; s_[i][1] += q4.y * k1v.y;
                s_[i][1] += q4.z * k2v.y; s_[i][1] += q4.w * k3v.y;
                s_[i][2] += q4.x * k0v.z; s_[i][2] += q4.y * k1v.z;
                s_[i][2] += q4.z * k2v.z; s_[i][2] += q4.w * k3v.z;
                s_[i][3] += q4.x * k0v.w; s_[i][3] += q4.y * k1v.w;
                s_[i][3] += q4.z * k2v.w; s_[i][3] += q4.w * k3v.w;
            }
        }

        // mask + scale + online softmax
        float mv[4];
#pragma unroll
        for (int j = 0; j < 4; j++) mv[j] = Mf[tx * 4 + j];

#pragma unroll
        for (int i = 0; i < 4; i++) {
#pragma unroll
            for (int j = 0; j < 4; j++) {
                s_[i][j] *= 0.125f;                       // 1/sqrt(64)
                if (mv[j] == 0.f) s_[i][j] = -1e30f;
            }
            float rm = fmaxf(fmaxf(s_[i][0], s_[i][1]), fmaxf(s_[i][2], s_[i][3]));
#pragma unroll
            for (int off = 8; off > 0; off >>= 1)
                rm = fmaxf(rm, __shfl_xor_sync(0xffffffffu, rm, off, 16));
            const float mn    = fmaxf(m_i[i], rm);
            const float alpha = __expf(m_i[i] - mn);
            m_i[i] = mn;
            float rs = 0.f;
#pragma unroll
            for (int j = 0; j < 4; j++) {
                float p = __expf(s_[i][j] - mn) * mv[j];  // masked -> exactly 0
                s_[i][j] = p;
                rs += p;
            }
#pragma unroll
            for (int off = 8; off > 0; off >>= 1)
                rs += __shfl_xor_sync(0xffffffffu, rs, off, 16);
            l_i[i] = l_i[i] * alpha + rs;
#pragma unroll
            for (int j = 0; j < 4; j++) o_[i][j] *= alpha;
            // stage P row fragment
            *(float4*)&Ps[(ty * 4 + i) * KTPAD + tx * 4] = *(float4*)&s_[i][0];
        }
        __syncthreads();

        // O += P @ V   (thread owns d = tx*4+j)
#pragma unroll 8
        for (int kj = 0; kj < 64; kj++) {
            float4 v4 = *(const float4*)&Vs[kj * 64 + tx * 4];
#pragma unroll
            for (int i = 0; i < 4; i++) {
                float p = Ps[(ty * 4 + i) * KTPAD + kj];
                o_[i][0] += p * v4.x;
                o_[i][1] += p * v4.y;
                o_[i][2] += p * v4.z;
                o_[i][3] += p * v4.w;
            }
        }
    }

    // normalize + store to [b,s,h*64+d]
#pragma unroll
    for (int i = 0; i < 4; i++) {
        const float inv = 1.0f / l_i[i];
        const int srow  = qblk * 64 + ty * 4 + i;
        float4 ov;
        ov.x = o_[i][0] * inv; ov.y = o_[i][1] * inv;
        ov.z = o_[i][2] * inv; ov.w = o_[i][3] * inv;
        *(float4*)&g_attn[((long)b * S_ + srow) * E_ + h * 64 + tx * 4] = ov;
    }
}

// ---------------------------------------------------------------------------
extern "C" void kernel_launch(void* const* d_in, const int* in_sizes, int n_in,
                              void* d_out, int out_size)
{
    const float* hidden = (const float*)d_in[0];   // [4,2048,1024]
    const float* qkv_w  = (const float*)d_in[1];   // [1024,3072]
    const float* qkv_b  = (const float*)d_in[2];   // [3072]
    const float* wo_w   = (const float*)d_in[3];   // [1024,1024]
    const float* wo_b   = (const float*)d_in[4];   // [1024]
    const int*   mask   = (const int*)d_in[5];     // [4,2048] int32
    float* out = (float*)d_out;

    // 1) QKV projection -> q/k/v [b,h,s,d]
    sgemm128<1><<<dim3(E3_ / 128, (B_ * S_) / 128), 256>>>(
        hidden, qkv_w, qkv_b, nullptr, B_ * S_, E3_, E_);

    // 2) attention -> g_attn [b,s,e]
    cudaFuncSetAttribute(attn_kernel,
                         cudaFuncAttributeMaxDynamicSharedMemorySize, ATTN_SMEM);
    attn_kernel<<<dim3(S_ / 64, BH_), 256, ATTN_SMEM>>>(mask);

    // 3) output projection
    float* attnp = nullptr;
    cudaGetSymbolAddress((void**)&attnp, g_attn);
    sgemm128<0><<<dim3(E_ / 128, (B_ * S_) / 128), 256>>>(
        attnp, wo_w, wo_b, out, B_ * S_, E_, E_);
}

// round 5
// speedup vs baseline: 2.6136x; 2.6136x over previous
#include <cuda_runtime.h>
#include <cuda_bf16.h>
#include <math.h>
#include <stdint.h>

#define B_ 4
#define S_ 2048
#define H_ 16
#define D_ 64
#define E_ 1024
#define E3_ 3072
#define BH_ (B_*H_)
#define M_ (B_*S_)   // 8192

// ---------------- device-global scratch (allocation-free rule) ----------------
__device__ __nv_bfloat16 g_hidh[M_*E_],  g_hidl[M_*E_];     // hidden split
__device__ __nv_bfloat16 g_wqh[E3_*E_],  g_wql[E3_*E_];     // qkv_w^T split [N][K]
__device__ __nv_bfloat16 g_woh[E_*E_],   g_wol[E_*E_];      // wo_w^T split  [N][K]
__device__ __nv_bfloat16 g_qh[BH_*S_*D_], g_ql[BH_*S_*D_];  // q (pre-scaled 0.125)
__device__ __nv_bfloat16 g_kh[BH_*S_*D_], g_kl[BH_*S_*D_];
__device__ __nv_bfloat16 g_vh[BH_*S_*D_], g_vl[BH_*S_*D_];
__device__ __nv_bfloat16 g_ah[M_*E_],    g_al[M_*E_];       // attn out split

// ---------------- helpers ----------------
__device__ __forceinline__ void ldsm4(uint32_t* r, uint32_t addr) {
    asm volatile("ldmatrix.sync.aligned.m8n8.x4.shared.b16 {%0,%1,%2,%3}, [%4];"
                 : "=r"(r[0]), "=r"(r[1]), "=r"(r[2]), "=r"(r[3]) : "r"(addr));
}
__device__ __forceinline__ void ldsm4t(uint32_t* r, uint32_t addr) {
    asm volatile("ldmatrix.sync.aligned.m8n8.x4.trans.shared.b16 {%0,%1,%2,%3}, [%4];"
                 : "=r"(r[0]), "=r"(r[1]), "=r"(r[2]), "=r"(r[3]) : "r"(addr));
}
__device__ __forceinline__ void mma16816(float* c, const uint32_t* a, const uint32_t* b) {
    asm volatile("mma.sync.aligned.m16n8k16.row.col.f32.bf16.bf16.f32 "
                 "{%0,%1,%2,%3}, {%4,%5,%6,%7}, {%8,%9}, {%0,%1,%2,%3};"
                 : "+f"(c[0]), "+f"(c[1]), "+f"(c[2]), "+f"(c[3])
                 : "r"(a[0]), "r"(a[1]), "r"(a[2]), "r"(a[3]),
                   "r"(b[0]), "r"(b[1]));
}
__device__ __forceinline__ void fsplit2(float a, float b, uint32_t& hi, uint32_t& lo) {
    __nv_bfloat162 h2 = __float22bfloat162_rn(make_float2(a, b));
    float ra = a - __bfloat162float(h2.x);
    float rb = b - __bfloat162float(h2.y);
    __nv_bfloat162 l2 = __float22bfloat162_rn(make_float2(ra, rb));
    hi = *reinterpret_cast<uint32_t*>(&h2);
    lo = *reinterpret_cast<uint32_t*>(&l2);
}

// ---------------- split kernels ----------------
__global__ void split4(const float* __restrict__ x,
                       __nv_bfloat16* __restrict__ hi, __nv_bfloat16* __restrict__ lo, int n)
{
    int i = (blockIdx.x * blockDim.x + threadIdx.x) * 4;
    if (i >= n) return;
    float4 v = *(const float4*)(x + i);
    uint32_t h0, l0, h1, l1;
    fsplit2(v.x, v.y, h0, l0);
    fsplit2(v.z, v.w, h1, l1);
    uint2 hh; hh.x = h0; hh.y = h1;
    uint2 ll; ll.x = l0; ll.y = l1;
    *(uint2*)(hi + i) = hh;
    *(uint2*)(lo + i) = ll;
}

// W [K][N] f32 -> Th/Tl [N][K] bf16
__global__ void tsplit(const float* __restrict__ W,
                       __nv_bfloat16* __restrict__ Th, __nv_bfloat16* __restrict__ Tl,
                       int K, int N)
{
    __shared__ float t[32][33];
    const int tx = threadIdx.x, ty = threadIdx.y;
    const int n0 = blockIdx.x * 32, k0 = blockIdx.y * 32;
#pragma unroll
    for (int j = 0; j < 4; j++)
        t[ty + j * 8][tx] = W[(size_t)(k0 + ty + j * 8) * N + n0 + tx];
    __syncthreads();
#pragma unroll
    for (int j = 0; j < 4; j++) {
        float v = t[tx][ty + j * 8];
        int n = n0 + ty + j * 8, k = k0 + tx;
        __nv_bfloat16 hv = __float2bfloat16(v);
        Th[(size_t)n * K + k] = hv;
        Tl[(size_t)n * K + k] = __float2bfloat16(v - __bfloat162float(hv));
    }
}

// ---------------- tensor-core GEMM: C[M,N] = A @ Bt^T + bias ----------------
// A split row-major [M][K]; Bt split row-major [N][K].  3-term bf16.
// EPI=1: scatter split Q/K/V [b,h,s,d] (Q scaled 0.125).  EPI=0: fp32 C.
template<int EPI>
__global__ __launch_bounds__(256)
void mma_gemm(const __nv_bfloat16* __restrict__ Ah, const __nv_bfloat16* __restrict__ Al,
              const __nv_bfloat16* __restrict__ Bth, const __nv_bfloat16* __restrict__ Btl,
              const float* __restrict__ bias, float* __restrict__ C,
              int M, int N, int K)
{
    extern __shared__ char sm[];
    const uint32_t sb = (uint32_t)__cvta_generic_to_shared(sm);
    const int tid = threadIdx.x, lane = tid & 31, wid = tid >> 5;
    const int wm = wid >> 1, wn = wid & 1;
    const int bm = blockIdx.y * 128, bn = blockIdx.x * 128;

    float acc[2][8][4];
#pragma unroll
    for (int mi = 0; mi < 2; mi++)
#pragma unroll
        for (int nb = 0; nb < 8; nb++)
#pragma unroll
            for (int q = 0; q < 4; q++) acc[mi][nb][q] = 0.f;

    const int lr = (lane & 7) + ((lane >> 3) & 1) * 8;

    for (int kt = 0; kt < K; kt += 64) {
        __syncthreads();
#pragma unroll
        for (int i = 0; i < 4; i++) {
            int idx = tid + i * 256;
            int row = idx >> 3, ch = idx & 7;
            uint32_t soff = row * 128 + ((ch ^ (row & 7)) << 4);
            size_t ga = (size_t)(bm + row) * K + kt + ch * 8;
            size_t gb = (size_t)(bn + row) * K + kt + ch * 8;
            *(uint4*)(sm + soff)         = *(const uint4*)(Ah + ga);
            *(uint4*)(sm + 16384 + soff) = *(const uint4*)(Al + ga);
            *(uint4*)(sm + 32768 + soff) = *(const uint4*)(Bth + gb);
            *(uint4*)(sm + 49152 + soff) = *(const uint4*)(Btl + gb);
        }
        __syncthreads();
#pragma unroll
        for (int kk = 0; kk < 4; kk++) {
            const int lc = kk * 2 + (lane >> 4);
            uint32_t afh[2][4], afl[2][4];
#pragma unroll
            for (int mi = 0; mi < 2; mi++) {
                int r = wm * 32 + mi * 16 + lr;
                uint32_t ad = sb + r * 128 + ((lc ^ (r & 7)) << 4);
                ldsm4(afh[mi], ad);
                ldsm4(afl[mi], ad + 16384);
            }
            uint32_t bfh[8][2], bfl[8][2], t4[4];
#pragma unroll
            for (int g = 0; g < 4; g++) {
                int r = wn * 64 + g * 16 + lr;
                uint32_t ad = sb + 32768 + r * 128 + ((lc ^ (r & 7)) << 4);
                ldsm4(t4, ad);
                bfh[2*g][0] = t4[0]; bfh[2*g][1] = t4[2];
                bfh[2*g+1][0] = t4[1]; bfh[2*g+1][1] = t4[3];
                ldsm4(t4, ad + 16384);
                bfl[2*g][0] = t4[0]; bfl[2*g][1] = t4[2];
                bfl[2*g+1][0] = t4[1]; bfl[2*g+1][1] = t4[3];
            }
#pragma unroll
            for (int mi = 0; mi < 2; mi++)
#pragma unroll
                for (int nb = 0; nb < 8; nb++) {
                    mma16816(acc[mi][nb], afh[mi], bfh[nb]);
                    mma16816(acc[mi][nb], afl[mi], bfh[nb]);
                    mma16816(acc[mi][nb], afh[mi], bfl[nb]);
                }
        }
    }

    // epilogue
#pragma unroll
    for (int mi = 0; mi < 2; mi++) {
        const int rbase = bm + wm * 32 + mi * 16 + (lane >> 2);
#pragma unroll
        for (int nb = 0; nb < 8; nb++) {
            const int cc = bn + wn * 64 + nb * 8 + (lane & 3) * 2;
            const float b0 = bias[cc], b1 = bias[cc + 1];
#pragma unroll
            for (int hr = 0; hr < 2; hr++) {
                const int r = rbase + hr * 8;
                float v0 = acc[mi][nb][hr * 2 + 0] + b0;
                float v1 = acc[mi][nb][hr * 2 + 1] + b1;
                if (EPI == 1) {
                    const int bb = r >> 11, si = r & 2047;
                    const int sec = cc >> 10, win = cc & 1023;
                    const int hh = win >> 6, dd = win & 63;
                    __nv_bfloat16 *dh, *dl;
                    if (sec == 0) { v0 *= 0.125f; v1 *= 0.125f; dh = g_qh; dl = g_ql; }
                    else if (sec == 1) { dh = g_kh; dl = g_kl; }
                    else { dh = g_vh; dl = g_vl; }
                    uint32_t hi, lo;
                    fsplit2(v0, v1, hi, lo);
                    size_t off = (((size_t)bb * H_ + hh) * S_ + si) * D_ + dd;
                    *(uint32_t*)(dh + off) = hi;
                    *(uint32_t*)(dl + off) = lo;
                } else {
                    float2 v; v.x = v0; v.y = v1;
                    *(float2*)(C + (size_t)r * N + cc) = v;
                }
            }
        }
    }
}

// ---------------- flash attention with mma (3-term bf16) ----------------
// block = 128 thr (4 warps), 64 queries per block, key tiles of 64.
// smem: Qh 0 | Ql 8K | Kh 16K | Kl 24K | Vh 32K | Vl 40K | Mf 48K(256B)
#define ATTN_SMEM (49152 + 256)

__global__ __launch_bounds__(128)
void attn_mma(const int* __restrict__ mask)
{
    extern __shared__ char sm[];
    const uint32_t sb = (uint32_t)__cvta_generic_to_shared(sm);
    float* Mf = (float*)(sm + 49152);
    const int tid = threadIdx.x, lane = tid & 31, w = tid >> 5;
    const int qb = blockIdx.x * 64, bh = blockIdx.y;
    const int b = bh >> 4, h = bh & 15;
    const size_t base = (size_t)bh * S_ * D_;
    const int lr = (lane & 7) + ((lane >> 3) & 1) * 8;

    // stage Q tile (hi, lo)
    for (int i = tid; i < 512; i += 128) {
        int row = i >> 3, ch = i & 7;
        uint32_t soff = row * 128 + ((ch ^ (row & 7)) << 4);
        size_t g = base + (size_t)(qb + row) * D_ + ch * 8;
        *(uint4*)(sm + soff)        = *(const uint4*)(g_qh + g);
        *(uint4*)(sm + 8192 + soff) = *(const uint4*)(g_ql + g);
    }
    __syncthreads();

    uint32_t qfh[4][4], qfl[4][4];
#pragma unroll
    for (int kk = 0; kk < 4; kk++) {
        int r = w * 16 + lr;
        int c = kk * 2 + (lane >> 4);
        uint32_t ad = sb + r * 128 + ((c ^ (r & 7)) << 4);
        ldsm4(qfh[kk], ad);
        ldsm4(qfl[kk], ad + 8192);
    }

    float O[8][4];
#pragma unroll
    for (int nb = 0; nb < 8; nb++)
#pragma unroll
        for (int q = 0; q < 4; q++) O[nb][q] = 0.f;
    float m0 = -1e30f, m1 = -1e30f, l0 = 0.f, l1 = 0.f;

    for (int kt = 0; kt < S_; kt += 64) {
        __syncthreads();
        for (int i = tid; i < 512; i += 128) {
            int row = i >> 3, ch = i & 7;
            uint32_t soff = row * 128 + ((ch ^ (row & 7)) << 4);
            size_t g = base + (size_t)(kt + row) * D_ + ch * 8;
            *(uint4*)(sm + 16384 + soff) = *(const uint4*)(g_kh + g);
            *(uint4*)(sm + 24576 + soff) = *(const uint4*)(g_kl + g);
            *(uint4*)(sm + 32768 + soff) = *(const uint4*)(g_vh + g);
            *(uint4*)(sm + 40960 + soff) = *(const uint4*)(g_vl + g);
        }
        if (tid < 64) Mf[tid] = mask[b * S_ + kt + tid] ? 1.0f : 0.0f;
        __syncthreads();

        // S = Q K^T (Q already scaled by 0.125)
        float S[8][4];
#pragma unroll
        for (int nb = 0; nb < 8; nb++)
#pragma unroll
            for (int q = 0; q < 4; q++) S[nb][q] = 0.f;
#pragma unroll
        for (int kk = 0; kk < 4; kk++) {
            const int lc = kk * 2 + (lane >> 4);
            uint32_t bfh[8][2], bfl[8][2], t4[4];
#pragma unroll
            for (int g = 0; g < 4; g++) {
                int r = g * 16 + lr;
                uint32_t ad = sb + 16384 + r * 128 + ((lc ^ (r & 7)) << 4);
                ldsm4(t4, ad);
                bfh[2*g][0] = t4[0]; bfh[2*g][1] = t4[2];
                bfh[2*g+1][0] = t4[1]; bfh[2*g+1][1] = t4[3];
                ldsm4(t4, ad + 8192);
                bfl[2*g][0] = t4[0]; bfl[2*g][1] = t4[2];
                bfl[2*g+1][0] = t4[1]; bfl[2*g+1][1] = t4[3];
            }
#pragma unroll
            for (int nb = 0; nb < 8; nb++) {
                mma16816(S[nb], qfh[kk], bfh[nb]);
                mma16816(S[nb], qfl[kk], bfh[nb]);
                mma16816(S[nb], qfh[kk], bfl[nb]);
            }
        }

        // mask + online softmax (rows g and g+8)
        float mk0[8], mk1[8];
#pragma unroll
        for (int nb = 0; nb < 8; nb++) {
            int c = nb * 8 + (lane & 3) * 2;
            mk0[nb] = Mf[c]; mk1[nb] = Mf[c + 1];
        }
        float mx0 = -1e30f, mx1 = -1e30f;
#pragma unroll
        for (int nb = 0; nb < 8; nb++) {
            S[nb][0] = (mk0[nb] != 0.f) ? S[nb][0] : -1e30f;
            S[nb][1] = (mk1[nb] != 0.f) ? S[nb][1] : -1e30f;
            S[nb][2] = (mk0[nb] != 0.f) ? S[nb][2] : -1e30f;
            S[nb][3] = (mk1[nb] != 0.f) ? S[nb][3] : -1e30f;
            mx0 = fmaxf(mx0, fmaxf(S[nb][0], S[nb][1]));
            mx1 = fmaxf(mx1, fmaxf(S[nb][2], S[nb][3]));
        }
        mx0 = fmaxf(mx0, __shfl_xor_sync(0xffffffffu, mx0, 1));
        mx0 = fmaxf(mx0, __shfl_xor_sync(0xffffffffu, mx0, 2));
        mx1 = fmaxf(mx1, __shfl_xor_sync(0xffffffffu, mx1, 1));
        mx1 = fmaxf(mx1, __shfl_xor_sync(0xffffffffu, mx1, 2));
        const float mn0 = fmaxf(m0, mx0), mn1 = fmaxf(m1, mx1);
        const float a0 = __expf(m0 - mn0), a1 = __expf(m1 - mn1);
        m0 = mn0; m1 = mn1;
        float s0 = 0.f, s1 = 0.f;
#pragma unroll
        for (int nb = 0; nb < 8; nb++) {
            float p0 = __expf(S[nb][0] - mn0) * mk0[nb];
            float p1 = __expf(S[nb][1] - mn0) * mk1[nb];
            float p2 = __expf(S[nb][2] - mn1) * mk0[nb];
            float p3 = __expf(S[nb][3] - mn1) * mk1[nb];
            S[nb][0] = p0; S[nb][1] = p1; S[nb][2] = p2; S[nb][3] = p3;
            s0 += p0 + p1; s1 += p2 + p3;
        }
        s0 += __shfl_xor_sync(0xffffffffu, s0, 1);
        s0 += __shfl_xor_sync(0xffffffffu, s0, 2);
        s1 += __shfl_xor_sync(0xffffffffu, s1, 1);
        s1 += __shfl_xor_sync(0xffffffffu, s1, 2);
        l0 = l0 * a0 + s0; l1 = l1 * a1 + s1;
#pragma unroll
        for (int nb = 0; nb < 8; nb++) {
            O[nb][0] *= a0; O[nb][1] *= a0; O[nb][2] *= a1; O[nb][3] *= a1;
        }

        // O += P V   (P frags from score accumulators, V via ldmatrix.trans)
#pragma unroll
        for (int kk = 0; kk < 4; kk++) {
            uint32_t ph[4], pl[4];
            fsplit2(S[2*kk][0],   S[2*kk][1],   ph[0], pl[0]);
            fsplit2(S[2*kk][2],   S[2*kk][3],   ph[1], pl[1]);
            fsplit2(S[2*kk+1][0], S[2*kk+1][1], ph[2], pl[2]);
            fsplit2(S[2*kk+1][2], S[2*kk+1][3], ph[3], pl[3]);
            uint32_t vfh[8][2], vfl[8][2], t4[4];
#pragma unroll
            for (int g = 0; g < 4; g++) {
                int r = kk * 16 + lr;
                int c = g * 2 + (lane >> 4);
                uint32_t ad = sb + 32768 + r * 128 + ((c ^ (r & 7)) << 4);
                ldsm4t(t4, ad);
                vfh[2*g][0] = t4[0]; vfh[2*g][1] = t4[1];
                vfh[2*g+1][0] = t4[2]; vfh[2*g+1][1] = t4[3];
                ldsm4t(t4, ad + 8192);
                vfl[2*g][0] = t4[0]; vfl[2*g][1] = t4[1];
                vfl[2*g+1][0] = t4[2]; vfl[2*g+1][1] = t4[3];
            }
#pragma unroll
            for (int nb = 0; nb < 8; nb++) {
                mma16816(O[nb], ph, vfh[nb]);
                mma16816(O[nb], pl, vfh[nb]);
                mma16816(O[nb], ph, vfl[nb]);
            }
        }
    }

    // epilogue: normalize, split, store attn [b,s,e] hi/lo
    const float inv0 = 1.0f / l0, inv1 = 1.0f / l1;
    const int s0r = qb + w * 16 + (lane >> 2);
#pragma unroll
    for (int nb = 0; nb < 8; nb++) {
        const int d = nb * 8 + (lane & 3) * 2;
        uint32_t hi, lo;
        size_t off = ((size_t)b * S_ + s0r) * E_ + h * 64 + d;
        fsplit2(O[nb][0] * inv0, O[nb][1] * inv0, hi, lo);
        *(uint32_t*)(g_ah + off) = hi;
        *(uint32_t*)(g_al + off) = lo;
        off += (size_t)8 * E_;
        fsplit2(O[nb][2] * inv1, O[nb][3] * inv1, hi, lo);
        *(uint32_t*)(g_ah + off) = hi;
        *(uint32_t*)(g_al + off) = lo;
    }
}

// ---------------------------------------------------------------------------
extern "C" void kernel_launch(void* const* d_in, const int* in_sizes, int n_in,
                              void* d_out, int out_size)
{
    const float* hidden = (const float*)d_in[0];
    const float* qkv_w  = (const float*)d_in[1];
    const float* qkv_b  = (const float*)d_in[2];
    const float* wo_w   = (const float*)d_in[3];
    const float* wo_b   = (const float*)d_in[4];
    const int*   mask   = (const int*)d_in[5];
    float* out = (float*)d_out;

    __nv_bfloat16 *hidh, *hidl, *wqh, *wql, *woh, *wol, *ah, *al;
    cudaGetSymbolAddress((void**)&hidh, g_hidh);
    cudaGetSymbolAddress((void**)&hidl, g_hidl);
    cudaGetSymbolAddress((void**)&wqh,  g_wqh);
    cudaGetSymbolAddress((void**)&wql,  g_wql);
    cudaGetSymbolAddress((void**)&woh,  g_woh);
    cudaGetSymbolAddress((void**)&wol,  g_wol);
    cudaGetSymbolAddress((void**)&ah,   g_ah);
    cudaGetSymbolAddress((void**)&al,   g_al);

    cudaFuncSetAttribute(mma_gemm<1>, cudaFuncAttributeMaxDynamicSharedMemorySize, 65536);
    cudaFuncSetAttribute(mma_gemm<0>, cudaFuncAttributeMaxDynamicSharedMemorySize, 65536);
    cudaFuncSetAttribute(attn_mma,    cudaFuncAttributeMaxDynamicSharedMemorySize, ATTN_SMEM);

    // 1) splits
    split4<<<(M_ * E_) / 4 / 256, 256>>>(hidden, hidh, hidl, M_ * E_);
    tsplit<<<dim3(E3_ / 32, E_ / 32), dim3(32, 8)>>>(qkv_w, wqh, wql, E_, E3_);
    tsplit<<<dim3(E_ / 32, E_ / 32),  dim3(32, 8)>>>(wo_w,  woh, wol, E_, E_);

    // 2) QKV projection -> split q/k/v [b,h,s,d]
    mma_gemm<1><<<dim3(E3_ / 128, M_ / 128), 256, 65536>>>(
        hidh, hidl, wqh, wql, qkv_b, nullptr, M_, E3_, E_);

    // 3) attention -> split attn [b,s,e]
    attn_mma<<<dim3(S_ / 64, BH_), 128, ATTN_SMEM>>>(mask);

    // 4) output projection -> fp32 out
    mma_gemm<0><<<dim3(E_ / 128, M_ / 128), 256, 65536>>>(
        ah, al, woh, wol, wo_b, out, M_, E_, E_);
}